// round 3
// baseline (speedup 1.0000x reference)
#include <cuda_runtime.h>
#include <cstdint>

#define N_NODES 50000
#define DS 127
#define DPAD 128
#define NE 800000
#define EPSF 1e-7f
#define GR 64   // rows per gemm block

// Padded scratch (stride 128 floats).
// g_h  : h1 = relu(agg1)+x after layer-2 gemm prologue writes it; pad col = 0
// g_z  : gemm output, pad col = 0 (w/b pad are zeroed)
// g_agg: atomic accumulation target; pad col garbage, never read
__device__ __align__(16) float g_h[N_NODES * DPAD];
__device__ __align__(16) float g_z[N_NODES * DPAD];
__device__ __align__(16) float g_agg[N_NODES * DPAD];

// smem float layout: W_s[127*128] | b_s[128] | h2_s (duplicated float2, 64 rows x 128 k)
#define W_ELE (DS * DPAD)            // 16256 floats
#define B_OFF W_ELE
#define H_OFF (W_ELE + DPAD)         // 16384 floats -> byte 65536 (16B aligned)
#define SMEM_BYTES ((H_OFF + GR * DPAD * 2) * 4)   // 131072 B

__device__ __forceinline__ float warp_sum(float v) {
#pragma unroll
    for (int o = 16; o; o >>= 1) v += __shfl_xor_sync(0xffffffffu, v, o);
    return v;
}

extern __shared__ float smem[];

// z = h @ W + b; agg zeroed in epilogue.
// layer==0: h rows come from x directly (h0 == logmap0(expmap0(x)) == x).
// layer==1: h rows = relu(agg) + x (== h1), also stored to g_h for the final skip.
// 256 threads, 64 rows/block. Thread (cx=tid&31, ry=tid>>5): 8 rows x 4 cols,
// accumulated as packed f32x2 pairs (cols 4cx..4cx+3).
__global__ void k_gemm(const float* __restrict__ W, const float* __restrict__ b,
                       const float* __restrict__ x, int layer) {
    float*  W_s = smem;
    float*  b_s = smem + B_OFF;
    float2* h2s = (float2*)(smem + H_OFF);
    int tid  = threadIdx.x;
    int row0 = blockIdx.x * GR;

    // W (pad col 127 -> 0), coalesced
    for (int i = tid; i < W_ELE; i += 256) {
        int k = i >> 7, c = i & 127;
        W_s[i] = (c < DS) ? W[k * DS + c] : 0.f;
    }
    if (tid < DPAD) b_s[tid] = (tid < DS) ? b[tid] : 0.f;

    // h tile, duplicated {v,v} for packed-FMA broadcast
    {
        int c = tid & 127, rr = tid >> 7;
        for (int r = rr; r < GR; r += 2) {
            int row = row0 + r;
            float v = 0.f;
            if (row < N_NODES) {
                if (c < DS) {
                    v = x[row * DS + c];
                    if (layer) {
                        v += fmaxf(g_agg[row * DPAD + c], 0.f);
                        g_h[row * DPAD + c] = v;
                    }
                } else if (layer) {
                    g_h[row * DPAD + c] = 0.f;   // pad col of h1
                }
            }
            h2s[r * DPAD + c] = make_float2(v, v);
        }
    }
    __syncthreads();

    int cx = tid & 31;
    int ry = tid >> 5;

    unsigned ws_addr = (unsigned)__cvta_generic_to_shared(W_s) + cx * 16;
    unsigned hs_addr = (unsigned)__cvta_generic_to_shared(h2s) + ry * 8 * DPAD * 8;

    unsigned long long acc[16];
#pragma unroll
    for (int i = 0; i < 16; i++) acc[i] = 0ull;

#pragma unroll 4
    for (int k = 0; k < DS; k++) {
        unsigned long long w01, w23;
        asm("ld.shared.v2.b64 {%0,%1}, [%2];"
            : "=l"(w01), "=l"(w23) : "r"(ws_addr + (unsigned)(k * 512)));
#pragma unroll
        for (int r = 0; r < 8; r++) {
            unsigned long long hv;
            asm("ld.shared.b64 %0, [%1];"
                : "=l"(hv) : "r"(hs_addr + (unsigned)(r * 1024 + k * 8)));
            asm("fma.rn.f32x2 %0, %1, %2, %0;" : "+l"(acc[2*r])     : "l"(hv), "l"(w01));
            asm("fma.rn.f32x2 %0, %1, %2, %0;" : "+l"(acc[2*r + 1]) : "l"(hv), "l"(w23));
        }
    }

    float4 bb = ((const float4*)b_s)[cx];
    float4* z4 = (float4*)g_z;
    float4* a4 = (float4*)g_agg;
#pragma unroll
    for (int r = 0; r < 8; r++) {
        int row = row0 + ry * 8 + r;
        if (row < N_NODES) {
            float2 p0 = *(float2*)&acc[2*r];
            float2 p1 = *(float2*)&acc[2*r + 1];
            float4 o;
            o.x = p0.x + bb.x;
            o.y = p0.y + bb.y;
            o.z = p1.x + bb.z;
            o.w = p1.y + bb.w;
            z4[row * 32 + cx] = o;
            a4[row * 32 + cx] = make_float4(0.f, 0.f, 0.f, 0.f);
        }
    }
}

// Warp-per-edge: agg[dst] += w * z[src], float4 vector reductions.
__global__ void k_edge(const int* __restrict__ src, const int* __restrict__ dst,
                       const float* __restrict__ wt) {
    int g = blockIdx.x * blockDim.x + threadIdx.x;
    int e = g >> 5, lane = g & 31;
    if (e >= NE) return;
    int s = src[e];
    int d = dst[e];
    float w = wt[e];
    const float4* z4 = (const float4*)g_z;
    float4 v = z4[s * 32 + lane];
    float4* a = (float4*)g_agg + d * 32 + lane;
    asm volatile("red.global.add.v4.f32 [%0], {%1,%2,%3,%4};"
                 :: "l"(a), "f"(v.x * w), "f"(v.y * w), "f"(v.z * w), "f"(v.w * w)
                 : "memory");
}

// h2 = relu(agg2) + h1;  out = expmap0(h2): out[i,0]=cosh(n), out[i,1+c]=sinh(n)*h_c/n
__global__ void k_final(float* __restrict__ out) {
    int warp = (blockIdx.x * blockDim.x + threadIdx.x) >> 5;
    int lane = threadIdx.x & 31;
    if (warp >= N_NODES) return;
    float v[4];
    float n2 = 0.f;
#pragma unroll
    for (int j = 0; j < 4; j++) {
        int c = lane + 32 * j;
        float a  = g_agg[warp * DPAD + c];
        float hv = g_h[warp * DPAD + c];
        v[j] = (c < DS) ? (fmaxf(a, 0.f) + hv) : 0.f;
        n2 += v[j] * v[j];
    }
    n2 = warp_sum(n2);
    float n = fmaxf(sqrtf(n2), EPSF);
    float t = coshf(n);
    float f = sinhf(n) / n;
    if (lane == 0) out[warp * DPAD] = t;
#pragma unroll
    for (int j = 0; j < 4; j++) {
        int c = lane + 32 * j;
        if (c < DS) out[warp * DPAD + 1 + c] = f * v[j];
    }
}

extern "C" void kernel_launch(void* const* d_in, const int* in_sizes, int n_in,
                              void* d_out, int out_size) {
    const float* x  = (const float*)d_in[0];
    const float* W1 = (const float*)d_in[1];
    const float* b1 = (const float*)d_in[2];
    const float* W2 = (const float*)d_in[3];
    const float* b2 = (const float*)d_in[4];
    const int*   es = (const int*)d_in[5];
    const int*   ed = (const int*)d_in[6];
    const float* ew = (const float*)d_in[7];
    float* out = (float*)d_out;

    cudaFuncSetAttribute(k_gemm, cudaFuncAttributeMaxDynamicSharedMemorySize, SMEM_BYTES);

    int gemm_blocks = (N_NODES + GR - 1) / GR;      // 782
    int edge_blocks = (NE * 32 + 255) / 256;        // 100000
    int row_blocks  = (N_NODES * 32 + 255) / 256;   // 6250

    k_gemm<<<gemm_blocks, 256, SMEM_BYTES>>>(W1, b1, x, 0);
    k_edge<<<edge_blocks, 256>>>(es, ed, ew);

    k_gemm<<<gemm_blocks, 256, SMEM_BYTES>>>(W2, b2, x, 1);
    k_edge<<<edge_blocks, 256>>>(es, ed, ew);

    k_final<<<row_blocks, 256>>>(out);
}

// round 4
// speedup vs baseline: 1.4046x; 1.4046x over previous
#include <cuda_runtime.h>

#define N_NODES 50000
#define DS 127
#define DPAD 128
#define NE 800000
#define EPSF 1e-7f
#define GR 64   // rows per gemm block

// Padded scratch (stride 128 floats).
// g_h  : h1 = relu(agg1)+x, written by layer-2 gemm prologue; pad col = 0
// g_z  : gemm output, pad col = 0
// g_agg: atomic accumulation target; pad col garbage, never read
__device__ __align__(16) float g_h[N_NODES * DPAD];
__device__ __align__(16) float g_z[N_NODES * DPAD];
__device__ __align__(16) float g_agg[N_NODES * DPAD];

// smem: W_s[127*128] | h_s[64*128] | b_s[128]  = 24576 floats = 98304 B (2 CTAs/SM)
#define H_OFF (DS * DPAD)
#define B_OFF (H_OFF + GR * DPAD)
#define SMEM_BYTES ((B_OFF + DPAD) * 4)

__device__ __forceinline__ float warp_sum(float v) {
#pragma unroll
    for (int o = 16; o; o >>= 1) v += __shfl_xor_sync(0xffffffffu, v, o);
    return v;
}

extern __shared__ float smem[];

// z = h @ W + b; agg zeroed in epilogue.
// layer==0: h rows = x (logmap0(expmap0(x)) == x analytically).
// layer==1: h rows = relu(agg) + x (== h1), also stored to g_h for the final skip.
// 256 threads, 64 rows/block. Thread (cx=tid&31, ry=tid>>5): 8 rows x 4 cols.
__global__ void k_gemm(const float* __restrict__ W, const float* __restrict__ b,
                       const float* __restrict__ x, int layer) {
    float* W_s = smem;
    float* h_s = smem + H_OFF;
    float* b_s = smem + B_OFF;
    int tid  = threadIdx.x;
    int row0 = blockIdx.x * GR;

    // W (pad col 127 -> 0), coalesced
    for (int i = tid; i < DS * DPAD; i += 256) {
        int k = i >> 7, c = i & 127;
        W_s[i] = (c < DS) ? W[k * DS + c] : 0.f;
    }
    if (tid < DPAD) b_s[tid] = (tid < DS) ? b[tid] : 0.f;

    // h tile: from x (and agg for layer 1); pad col 127 -> 0
    {
        int c = tid & 127, rr = tid >> 7;
        for (int r = rr; r < GR; r += 2) {
            int row = row0 + r;
            float v = 0.f;
            if (row < N_NODES) {
                if (c < DS) {
                    v = x[row * DS + c];
                    if (layer) {
                        v += fmaxf(g_agg[row * DPAD + c], 0.f);
                        g_h[row * DPAD + c] = v;
                    }
                } else if (layer) {
                    g_h[row * DPAD + c] = 0.f;   // pad col of h1
                }
            }
            h_s[r * DPAD + c] = v;
        }
    }
    __syncthreads();

    int cx = tid & 31;
    int ry = tid >> 5;
    float4 acc[8];
#pragma unroll
    for (int r = 0; r < 8; r++) acc[r] = make_float4(0.f, 0.f, 0.f, 0.f);

    const float4* W4 = (const float4*)W_s;
#pragma unroll 4
    for (int k = 0; k < DS; k++) {
        float4 w = W4[k * 32 + cx];
#pragma unroll
        for (int r = 0; r < 8; r++) {
            float hv = h_s[(ry * 8 + r) * DPAD + k];  // warp-uniform broadcast
            acc[r].x += hv * w.x;
            acc[r].y += hv * w.y;
            acc[r].z += hv * w.z;
            acc[r].w += hv * w.w;
        }
    }

    float4 bb = ((const float4*)b_s)[cx];
    float4* z4 = (float4*)g_z;
    float4* a4 = (float4*)g_agg;
#pragma unroll
    for (int r = 0; r < 8; r++) {
        int row = row0 + ry * 8 + r;
        if (row < N_NODES) {
            float4 o;
            o.x = acc[r].x + bb.x;
            o.y = acc[r].y + bb.y;
            o.z = acc[r].z + bb.z;
            o.w = acc[r].w + bb.w;
            z4[row * 32 + cx] = o;
            a4[row * 32 + cx] = make_float4(0.f, 0.f, 0.f, 0.f);
        }
    }
}

// Warp processes 4 edges: lanes 0-3 load metadata, shuffle-broadcast, then
// 4 overlapped 512B row loads (MLP=4) followed by 4 vector reductions.
// NE % 4 == 0, grid sized exactly -> no bounds checks.
__global__ void k_edge(const int* __restrict__ src, const int* __restrict__ dst,
                       const float* __restrict__ wt) {
    int warp = (blockIdx.x * blockDim.x + threadIdx.x) >> 5;
    int lane = threadIdx.x & 31;
    int e0 = warp * 4;

    int s = 0, d = 0;
    float w = 0.f;
    if (lane < 4) {
        s = src[e0 + lane];
        d = dst[e0 + lane];
        w = wt[e0 + lane];
    }

    const float4* z4 = (const float4*)g_z;
    float4 v[4];
#pragma unroll
    for (int i = 0; i < 4; i++) {
        int si = __shfl_sync(0xffffffffu, s, i);
        v[i] = z4[si * 32 + lane];
    }
#pragma unroll
    for (int i = 0; i < 4; i++) {
        int   di = __shfl_sync(0xffffffffu, d, i);
        float wi = __shfl_sync(0xffffffffu, w, i);
        float4* a = (float4*)g_agg + di * 32 + lane;
        asm volatile("red.global.add.v4.f32 [%0], {%1,%2,%3,%4};"
                     :: "l"(a), "f"(v[i].x * wi), "f"(v[i].y * wi),
                        "f"(v[i].z * wi), "f"(v[i].w * wi)
                     : "memory");
    }
}

// h2 = relu(agg2) + h1;  out = expmap0(h2): out[i,0]=cosh(n), out[i,1+c]=sinh(n)*h_c/n
__global__ void k_final(float* __restrict__ out) {
    int warp = (blockIdx.x * blockDim.x + threadIdx.x) >> 5;
    int lane = threadIdx.x & 31;
    if (warp >= N_NODES) return;
    float v[4];
    float n2 = 0.f;
#pragma unroll
    for (int j = 0; j < 4; j++) {
        int c = lane + 32 * j;
        float a  = g_agg[warp * DPAD + c];
        float hv = g_h[warp * DPAD + c];
        v[j] = (c < DS) ? (fmaxf(a, 0.f) + hv) : 0.f;
        n2 += v[j] * v[j];
    }
    n2 = warp_sum(n2);
    float n = fmaxf(sqrtf(n2), EPSF);
    float t = coshf(n);
    float f = sinhf(n) / n;
    if (lane == 0) out[warp * DPAD] = t;
#pragma unroll
    for (int j = 0; j < 4; j++) {
        int c = lane + 32 * j;
        if (c < DS) out[warp * DPAD + 1 + c] = f * v[j];
    }
}

extern "C" void kernel_launch(void* const* d_in, const int* in_sizes, int n_in,
                              void* d_out, int out_size) {
    const float* x  = (const float*)d_in[0];
    const float* W1 = (const float*)d_in[1];
    const float* b1 = (const float*)d_in[2];
    const float* W2 = (const float*)d_in[3];
    const float* b2 = (const float*)d_in[4];
    const int*   es = (const int*)d_in[5];
    const int*   ed = (const int*)d_in[6];
    const float* ew = (const float*)d_in[7];
    float* out = (float*)d_out;

    cudaFuncSetAttribute(k_gemm, cudaFuncAttributeMaxDynamicSharedMemorySize, SMEM_BYTES);

    int gemm_blocks = (N_NODES + GR - 1) / GR;       // 782
    int edge_blocks = (NE / 4) / 8;                  // 25000 (8 warps/block, 4 edges/warp)
    int row_blocks  = (N_NODES * 32 + 255) / 256;    // 6250

    k_gemm<<<gemm_blocks, 256, SMEM_BYTES>>>(W1, b1, x, 0);
    k_edge<<<edge_blocks, 256>>>(es, ed, ew);

    k_gemm<<<gemm_blocks, 256, SMEM_BYTES>>>(W2, b2, x, 1);
    k_edge<<<edge_blocks, 256>>>(es, ed, ew);

    k_final<<<row_blocks, 256>>>(out);
}